// round 14
// baseline (speedup 1.0000x reference)
#include <cuda_runtime.h>
#include <cuda_fp16.h>
#include <math.h>
#include <stdint.h>

#define NTOK   2048
#define FEAT   1024
#define IN_CH  12544
#define NONGT  300
#define G      16
#define DG     64
#define EMB    64
#define GW_STRIDE (G * NONGT)   // 4800

// GEMM tile config: 128x128 CTA tile, BK=16, 512 threads, ldmatrix, 4-stage cp.async
#define ROWB   48
#define TILEB  (128 * ROWB)
#define STGB   (4 * TILEB)
#define GSMEM  (4 * STGB)        // 98304 B

// ---------------- fp32 scratch ----------------
__device__ float g_h   [NTOK * FEAT];
__device__ float g_h2  [NTOK * FEAT];
__device__ float g_q   [NTOK * FEAT];
__device__ float g_att [NTOK * FEAT];
__device__ float g_kp  [384 * 2048];
__device__ float g_w1  [NTOK * G * NONGT];
__device__ float g_w2  [NTOK * G * NONGT];
__device__ float g_aff [NTOK * G * NONGT];
__device__ float g_bkp [2048];

// ---------------- fp16 split scratch ----------------
__device__ __half g_xh [NTOK * IN_CH];
__device__ __half g_xl [NTOK * IN_CH];
__device__ __half g_w6h[FEAT * IN_CH];
__device__ __half g_w6l[FEAT * IN_CH];
__device__ __half g_w7h[FEAT * FEAT];
__device__ __half g_w7l[FEAT * FEAT];
__device__ __half g_qwh[FEAT * FEAT];
__device__ __half g_qwl[FEAT * FEAT];
__device__ __half g_kpwh[2048 * FEAT];
__device__ __half g_kpwl[2048 * FEAT];
__device__ __half g_ah [NTOK * FEAT];          // fc6 out / attn2 in
__device__ __half g_al [NTOK * FEAT];
__device__ __half g_bh [NTOK * FEAT];          // fc7 in
__device__ __half g_bl [NTOK * FEAT];
__device__ __half g_qsh[NTOK * FEAT];          // q split (aff A operand)
__device__ __half g_qsl[NTOK * FEAT];
__device__ __half g_kph[384 * 2048];           // kp split (aff B operand)
__device__ __half g_kpl[384 * 2048];

// ---------------- helpers ----------------
__device__ __forceinline__ uint32_t cvta_s(const void* p) {
    return (uint32_t)__cvta_generic_to_shared(p);
}
__device__ __forceinline__ void cp16(uint32_t s, const void* g) {
    asm volatile("cp.async.cg.shared.global [%0], [%1], 16;\n" :: "r"(s), "l"(g));
}
#define LDSM_X4(r0, r1, r2, r3, a)                                              \
    asm volatile("ldmatrix.sync.aligned.m8n8.x4.shared.b16 {%0,%1,%2,%3}, [%4];" \
                 : "=r"(r0), "=r"(r1), "=r"(r2), "=r"(r3) : "r"(a))
#define MMA16(ACC, A0, A1, A2, A3, B0, B1)                                      \
    asm volatile(                                                               \
        "mma.sync.aligned.m16n8k16.row.col.f32.f16.f16.f32 "                    \
        "{%0,%1,%2,%3}, {%4,%5,%6,%7}, {%8,%9}, {%0,%1,%2,%3};\n"               \
        : "+f"(ACC[0]), "+f"(ACC[1]), "+f"(ACC[2]), "+f"(ACC[3])                \
        : "r"(A0), "r"(A1), "r"(A2), "r"(A3), "r"(B0), "r"(B1))

// ---------------- fp16x3 GEMM, 512 threads: C = A[M,K] @ W[N,K]^T (+bias) ----
__global__ __launch_bounds__(512, 1)
void gemm_lm(const __half* __restrict__ Ah, const __half* __restrict__ Al,
             const __half* __restrict__ Wh, const __half* __restrict__ Wl,
             const float* __restrict__ bias, float* __restrict__ C,
             __half2* __restrict__ dH, __half2* __restrict__ dL,
             int M, int N, int K) {
    extern __shared__ char dsm[];
    const uint32_t sbase = cvta_s(dsm);

    const int tid  = threadIdx.x;
    const int lane = tid & 31;
    const int wid  = tid >> 5;
    const int wm   = wid >> 2;
    const int wn   = wid & 3;
    const int qd   = lane >> 2;
    const int tg   = lane & 3;
    const int bm   = blockIdx.y * 128;
    const int bn   = blockIdx.x * 128;

    const int lrow = (tid & 255) >> 1;
    const int lch  = tid & 1;
    const bool isA = tid < 256;
    const __half* gH = (isA ? Ah + (size_t)(bm + lrow) * K
                            : Wh + (size_t)(bn + lrow) * K) + lch * 8;
    const __half* gL = (isA ? Al + (size_t)(bm + lrow) * K
                            : Wl + (size_t)(bn + lrow) * K) + lch * 8;
    const uint32_t woffH = (uint32_t)((isA ? 0 : 2 * TILEB) + lrow * ROWB + lch * 16);

    const uint32_t aRow  = (uint32_t)(wm * 32 + (lane & 7) + ((lane >> 3) & 1) * 8);
    const uint32_t aByte = (uint32_t)(((lane >> 4) & 1) * 16);
    const uint32_t bRow  = (uint32_t)(wn * 32 + ((lane >> 4) & 1) * 8 + (lane & 7));
    const uint32_t bByte = (uint32_t)(((lane >> 3) & 1) * 16);

    float acc[2][4][4];
#pragma unroll
    for (int i = 0; i < 2; i++)
#pragma unroll
        for (int j = 0; j < 4; j++)
#pragma unroll
            for (int r = 0; r < 4; r++) acc[i][j][r] = 0.f;

    const int nk = K / 16;

    auto load_stage = [&](int kt) {
        const uint32_t st = sbase + (uint32_t)(kt & 3) * STGB;
        const size_t k0 = (size_t)kt * 16;
        cp16(st + woffH, gH + k0);
        cp16(st + TILEB + woffH, gL + k0);
    };

#pragma unroll
    for (int s = 0; s < 3; s++) {
        if (s < nk) load_stage(s);
        asm volatile("cp.async.commit_group;\n");
    }

    for (int kt = 0; kt < nk; kt++) {
        asm volatile("cp.async.wait_group 2;\n");
        __syncthreads();
        if (kt + 3 < nk) load_stage(kt + 3);
        asm volatile("cp.async.commit_group;\n");

        const uint32_t st = sbase + (uint32_t)(kt & 3) * STGB;

        uint32_t ah[2][4], al_[2][4], bh[4][2], bl[4][2];
#pragma unroll
        for (int mi = 0; mi < 2; mi++) {
            const uint32_t ar = (aRow + mi * 16) * ROWB + aByte;
            LDSM_X4(ah[mi][0], ah[mi][1], ah[mi][2], ah[mi][3], st + ar);
            LDSM_X4(al_[mi][0], al_[mi][1], al_[mi][2], al_[mi][3], st + TILEB + ar);
        }
        {
            const uint32_t br = bRow * ROWB + bByte;
            uint32_t r0, r1, r2, r3;
            LDSM_X4(r0, r1, r2, r3, st + 2 * TILEB + br);
            bh[0][0] = r0; bh[0][1] = r1; bh[1][0] = r2; bh[1][1] = r3;
            LDSM_X4(r0, r1, r2, r3, st + 2 * TILEB + br + 16 * ROWB);
            bh[2][0] = r0; bh[2][1] = r1; bh[3][0] = r2; bh[3][1] = r3;
            LDSM_X4(r0, r1, r2, r3, st + 3 * TILEB + br);
            bl[0][0] = r0; bl[0][1] = r1; bl[1][0] = r2; bl[1][1] = r3;
            LDSM_X4(r0, r1, r2, r3, st + 3 * TILEB + br + 16 * ROWB);
            bl[2][0] = r0; bl[2][1] = r1; bl[3][0] = r2; bl[3][1] = r3;
        }

#pragma unroll
        for (int mi = 0; mi < 2; mi++)
#pragma unroll
            for (int ni = 0; ni < 4; ni++)
                MMA16(acc[mi][ni], al_[mi][0], al_[mi][1], al_[mi][2], al_[mi][3],
                      bh[ni][0], bh[ni][1]);
#pragma unroll
        for (int mi = 0; mi < 2; mi++)
#pragma unroll
            for (int ni = 0; ni < 4; ni++)
                MMA16(acc[mi][ni], ah[mi][0], ah[mi][1], ah[mi][2], ah[mi][3],
                      bl[ni][0], bl[ni][1]);
#pragma unroll
        for (int mi = 0; mi < 2; mi++)
#pragma unroll
            for (int ni = 0; ni < 4; ni++)
                MMA16(acc[mi][ni], ah[mi][0], ah[mi][1], ah[mi][2], ah[mi][3],
                      bh[ni][0], bh[ni][1]);
    }

#pragma unroll
    for (int mi = 0; mi < 2; mi++) {
        const int r0 = bm + wm * 32 + mi * 16 + qd;
#pragma unroll
        for (int ni = 0; ni < 4; ni++) {
            const int c0 = bn + wn * 32 + ni * 8 + tg * 2;
            const float b0 = bias ? bias[c0]     : 0.f;
            const float b1 = bias ? bias[c0 + 1] : 0.f;
#pragma unroll
            for (int half = 0; half < 2; half++) {
                const int r = r0 + half * 8;
                if (r < M) {
                    const float vx = acc[mi][ni][half * 2]     + b0;
                    const float vy = acc[mi][ni][half * 2 + 1] + b1;
                    const size_t idx = (size_t)r * N + c0;
                    *(float2*)(C + idx) = make_float2(vx, vy);
                    if (dH) {
                        __half2 h = __floats2half2_rn(vx, vy);
                        float2 f = __half22float2(h);
                        dH[idx >> 1] = h;
                        dL[idx >> 1] = __floats2half2_rn(vx - f.x, vy - f.y);
                    }
                }
            }
        }
    }
}

// ---------------- aff via tensor cores: Aff[n][g][m] = 0.125 * q.k (fp16x3) --
// A = q split [2048 x 1024] (lda=FEAT), B = kp split [384 x 2048] (ldb=2048),
// operand columns at g*64, K=64. Rows 300..383 of B are zero/stale: each output
// element only involves its own m row, discarded by the m<300 predicate.
__global__ __launch_bounds__(512, 1)
void aff_mma(const __half* __restrict__ Qh, const __half* __restrict__ Ql,
             const __half* __restrict__ Kh, const __half* __restrict__ Kl,
             float* __restrict__ Aff) {
    extern __shared__ char dsm[];
    const uint32_t sbase = cvta_s(dsm);

    const int tid  = threadIdx.x;
    const int lane = tid & 31;
    const int wid  = tid >> 5;
    const int wm   = wid >> 2;
    const int wn   = wid & 3;
    const int qd   = lane >> 2;
    const int tg   = lane & 3;
    const int g    = blockIdx.z;
    const int bm   = blockIdx.y * 128;   // n tile
    const int bn   = blockIdx.x * 128;   // m tile (0,128,256)

    const int lrow = (tid & 255) >> 1;
    const int lch  = tid & 1;
    const bool isA = tid < 256;
    const __half* gH = (isA ? Qh + (size_t)(bm + lrow) * FEAT
                            : Kh + (size_t)(bn + lrow) * 2048) + g * DG + lch * 8;
    const __half* gL = (isA ? Ql + (size_t)(bm + lrow) * FEAT
                            : Kl + (size_t)(bn + lrow) * 2048) + g * DG + lch * 8;
    const uint32_t woffH = (uint32_t)((isA ? 0 : 2 * TILEB) + lrow * ROWB + lch * 16);

    const uint32_t aRow  = (uint32_t)(wm * 32 + (lane & 7) + ((lane >> 3) & 1) * 8);
    const uint32_t aByte = (uint32_t)(((lane >> 4) & 1) * 16);
    const uint32_t bRow  = (uint32_t)(wn * 32 + ((lane >> 4) & 1) * 8 + (lane & 7));
    const uint32_t bByte = (uint32_t)(((lane >> 3) & 1) * 16);

    float acc[2][4][4];
#pragma unroll
    for (int i = 0; i < 2; i++)
#pragma unroll
        for (int j = 0; j < 4; j++)
#pragma unroll
            for (int r = 0; r < 4; r++) acc[i][j][r] = 0.f;

    auto load_stage = [&](int kt) {
        const uint32_t st = sbase + (uint32_t)(kt & 3) * STGB;
        const size_t k0 = (size_t)kt * 16;
        cp16(st + woffH, gH + k0);
        cp16(st + TILEB + woffH, gL + k0);
    };

#pragma unroll
    for (int s = 0; s < 3; s++) {
        load_stage(s);
        asm volatile("cp.async.commit_group;\n");
    }

#pragma unroll
    for (int kt = 0; kt < 4; kt++) {
        asm volatile("cp.async.wait_group 2;\n");
        __syncthreads();
        if (kt == 0) load_stage(3);
        asm volatile("cp.async.commit_group;\n");

        const uint32_t st = sbase + (uint32_t)(kt & 3) * STGB;

        uint32_t ah[2][4], al_[2][4], bh[4][2], bl[4][2];
#pragma unroll
        for (int mi = 0; mi < 2; mi++) {
            const uint32_t ar = (aRow + mi * 16) * ROWB + aByte;
            LDSM_X4(ah[mi][0], ah[mi][1], ah[mi][2], ah[mi][3], st + ar);
            LDSM_X4(al_[mi][0], al_[mi][1], al_[mi][2], al_[mi][3], st + TILEB + ar);
        }
        {
            const uint32_t br = bRow * ROWB + bByte;
            uint32_t r0, r1, r2, r3;
            LDSM_X4(r0, r1, r2, r3, st + 2 * TILEB + br);
            bh[0][0] = r0; bh[0][1] = r1; bh[1][0] = r2; bh[1][1] = r3;
            LDSM_X4(r0, r1, r2, r3, st + 2 * TILEB + br + 16 * ROWB);
            bh[2][0] = r0; bh[2][1] = r1; bh[3][0] = r2; bh[3][1] = r3;
            LDSM_X4(r0, r1, r2, r3, st + 3 * TILEB + br);
            bl[0][0] = r0; bl[0][1] = r1; bl[1][0] = r2; bl[1][1] = r3;
            LDSM_X4(r0, r1, r2, r3, st + 3 * TILEB + br + 16 * ROWB);
            bl[2][0] = r0; bl[2][1] = r1; bl[3][0] = r2; bl[3][1] = r3;
        }

#pragma unroll
        for (int mi = 0; mi < 2; mi++)
#pragma unroll
            for (int ni = 0; ni < 4; ni++)
                MMA16(acc[mi][ni], al_[mi][0], al_[mi][1], al_[mi][2], al_[mi][3],
                      bh[ni][0], bh[ni][1]);
#pragma unroll
        for (int mi = 0; mi < 2; mi++)
#pragma unroll
            for (int ni = 0; ni < 4; ni++)
                MMA16(acc[mi][ni], ah[mi][0], ah[mi][1], ah[mi][2], ah[mi][3],
                      bl[ni][0], bl[ni][1]);
#pragma unroll
        for (int mi = 0; mi < 2; mi++)
#pragma unroll
            for (int ni = 0; ni < 4; ni++)
                MMA16(acc[mi][ni], ah[mi][0], ah[mi][1], ah[mi][2], ah[mi][3],
                      bh[ni][0], bh[ni][1]);
    }

    // epilogue: Aff[n*4800 + g*300 + m], scale 0.125, m<300
#pragma unroll
    for (int mi = 0; mi < 2; mi++) {
        const int r0 = bm + wm * 32 + mi * 16 + qd;
#pragma unroll
        for (int ni = 0; ni < 4; ni++) {
            const int c0 = bn + wn * 32 + ni * 8 + tg * 2;
            if (c0 < NONGT) {
#pragma unroll
                for (int half = 0; half < 2; half++) {
                    const int r = r0 + half * 8;
                    float* dst = Aff + (size_t)r * GW_STRIDE + g * NONGT + c0;
                    *(float2*)dst = make_float2(0.125f * acc[mi][ni][half * 2],
                                                0.125f * acc[mi][ni][half * 2 + 1]);
                }
            }
        }
    }
}

// ---------------- split: fp32 -> (hi, lo) fp16 --------------------------------
__global__ void split_f16(const float4* __restrict__ src, __half2* __restrict__ dh,
                          __half2* __restrict__ dl, int n4) {
    int i = blockIdx.x * blockDim.x + threadIdx.x;
    if (i < n4) {
        float4 v = src[i];
        __half2 h0 = __floats2half2_rn(v.x, v.y);
        __half2 h1 = __floats2half2_rn(v.z, v.w);
        float2 f0 = __half22float2(h0);
        float2 f1 = __half22float2(h1);
        dh[i * 2]     = h0;
        dh[i * 2 + 1] = h1;
        dl[i * 2]     = __floats2half2_rn(v.x - f0.x, v.y - f0.y);
        dl[i * 2 + 1] = __floats2half2_rn(v.z - f1.x, v.w - f1.y);
    }
}

// ---------------- h2 = relu(a+b), emitted as fp16 split -----------------------
__global__ void addrelu_split(const float4* __restrict__ a, const float4* __restrict__ b,
                              __half2* __restrict__ dh, __half2* __restrict__ dl, int n4) {
    int i = blockIdx.x * blockDim.x + threadIdx.x;
    if (i < n4) {
        float4 x = a[i], y = b[i];
        float4 v;
        v.x = fmaxf(x.x + y.x, 0.f); v.y = fmaxf(x.y + y.y, 0.f);
        v.z = fmaxf(x.z + y.z, 0.f); v.w = fmaxf(x.w + y.w, 0.f);
        __half2 h0 = __floats2half2_rn(v.x, v.y);
        __half2 h1 = __floats2half2_rn(v.z, v.w);
        float2 f0 = __half22float2(h0);
        float2 f1 = __half22float2(h1);
        dh[i * 2]     = h0;
        dh[i * 2 + 1] = h1;
        dl[i * 2]     = __floats2half2_rn(v.x - f0.x, v.y - f0.y);
        dl[i * 2 + 1] = __floats2half2_rn(v.z - f1.x, v.w - f1.y);
    }
}

// ---------------- final: c = relu(a+b) fp32 -----------------------------------
__global__ void add_relu4(const float4* __restrict__ a, const float4* __restrict__ b,
                          float4* __restrict__ c, int n4) {
    int i = blockIdx.x * blockDim.x + threadIdx.x;
    if (i < n4) {
        float4 x = a[i], y = b[i];
        float4 r;
        r.x = fmaxf(x.x + y.x, 0.f); r.y = fmaxf(x.y + y.y, 0.f);
        r.z = fmaxf(x.z + y.z, 0.f); r.w = fmaxf(x.w + y.w, 0.f);
        c[i] = r;
    }
}

// ---------------- bias for fused k|P GEMM -------------------------------------
__global__ void build_bias_kp(const float* __restrict__ kb, float* __restrict__ dst) {
    int i = blockIdx.x * blockDim.x + threadIdx.x;
    if (i < 2048) dst[i] = (i < 1024) ? kb[i] : 0.f;
}

// ---------------- pos weights v3: register weights, broadcast pe --------------
// Lane l = layer*16+g holds its weight row in registers; warp w owns m-range.
__global__ __launch_bounds__(256)
void pos_dual(const float* __restrict__ pos_emb,
              const float* __restrict__ pw1, const float* __restrict__ pb1,
              const float* __restrict__ pw2, const float* __restrict__ pb2,
              float* __restrict__ W1, float* __restrict__ W2) {
    __shared__ float sOut[8][32][39];   // [warp][lane=(layer,g)][m-local], 39: conflict-free
    const int n    = blockIdx.x;
    const int tid  = threadIdx.x;
    const int lane = tid & 31;
    const int w    = tid >> 5;
    const int layer = lane >> 4;
    const int g     = lane & 15;

    // weight row -> registers (once)
    const float* pw = layer ? pw2 : pw1;
    float wreg[64];
#pragma unroll
    for (int e4 = 0; e4 < 16; e4++) {
        float4 v = __ldg((const float4*)(pw + g * 64 + e4 * 4));
        wreg[e4 * 4 + 0] = v.x; wreg[e4 * 4 + 1] = v.y;
        wreg[e4 * 4 + 2] = v.z; wreg[e4 * 4 + 3] = v.w;
    }
    const float bias = __ldg((layer ? pb2 : pb1) + g);

    const int m0   = w * 38;
    const int mcnt = min(38, NONGT - m0);   // last warp: 34
    const float4* pe4 = (const float4*)(pos_emb + (size_t)n * NONGT * EMB);

    for (int mi = 0; mi < mcnt; mi++) {
        const float4* row = pe4 + (size_t)(m0 + mi) * 16;
        float acc = bias;
#pragma unroll
        for (int e4 = 0; e4 < 16; e4++) {
            float4 p = __ldg(row + e4);   // broadcast: all lanes same address
            acc = fmaf(p.x, wreg[e4 * 4 + 0], acc);
            acc = fmaf(p.y, wreg[e4 * 4 + 1], acc);
            acc = fmaf(p.z, wreg[e4 * 4 + 2], acc);
            acc = fmaf(p.w, wreg[e4 * 4 + 3], acc);
        }
        sOut[w][lane][mi] = fmaxf(acc, 1e-6f);
    }
    __syncwarp();

    // coalesced writeback: 32 rows (layer,g) x mcnt
    const size_t nbase = (size_t)n * GW_STRIDE;
#pragma unroll 4
    for (int r = 0; r < 32; r++) {
        float* dst = ((r < 16) ? W1 : W2) + nbase + (r & 15) * NONGT + m0;
        for (int i = lane; i < mcnt; i += 32)
            dst[i] = sOut[w][r][i];
    }
}

// ---------------- softmax(w * e^aff) over m + out = s @ P_g + out_b ----------
__global__ __launch_bounds__(256)
void softmax_pv(const float* __restrict__ Wt, const float* __restrict__ Aff,
                const float* __restrict__ P, int ldp,
                const float* __restrict__ ob, float* __restrict__ Att) {
    const int g  = blockIdx.y;
    const int n0 = blockIdx.x * 16;
    __shared__ float s[16][301];
    const int tid = threadIdx.x, w = tid >> 5, lane = tid & 31;

#pragma unroll
    for (int rr = 0; rr < 2; rr++) {
        int r = w * 2 + rr;
        const float* srcW = Wt  + (size_t)(n0 + r) * GW_STRIDE + g * NONGT;
        const float* srcA = Aff + (size_t)(n0 + r) * GW_STRIDE + g * NONGT;
        float a[10], wv[10];
        float mx = -1e30f;
#pragma unroll
        for (int i = 0; i < 10; i++) {
            int m = lane + 32 * i;
            a[i]  = (m < NONGT) ? srcA[m] : -1e30f;
            wv[i] = (m < NONGT) ? srcW[m] : 0.f;
            mx = fmaxf(mx, a[i]);
        }
#pragma unroll
        for (int off = 16; off; off >>= 1) mx = fmaxf(mx, __shfl_xor_sync(~0u, mx, off));
        float sum = 0.f;
#pragma unroll
        for (int i = 0; i < 10; i++) {
            float e = wv[i] * __expf(a[i] - mx);
            a[i] = e;
            sum += e;
        }
#pragma unroll
        for (int off = 16; off; off >>= 1) sum += __shfl_xor_sync(~0u, sum, off);
        float inv = 1.f / sum;
#pragma unroll
        for (int i = 0; i < 10; i++) {
            int m = lane + 32 * i;
            if (m < NONGT) s[r][m] = a[i] * inv;
        }
    }
    __syncthreads();

    const int o = tid & 63, grp = tid >> 6;
    float acc0 = 0.f, acc1 = 0.f, acc2 = 0.f, acc3 = 0.f;
    const float* pcol = P + g * DG + o;
#pragma unroll 4
    for (int m = 0; m < NONGT; m++) {
        float p = __ldg(pcol + (size_t)m * ldp);
        acc0 = fmaf(s[grp][m],      p, acc0);
        acc1 = fmaf(s[grp + 4][m],  p, acc1);
        acc2 = fmaf(s[grp + 8][m],  p, acc2);
        acc3 = fmaf(s[grp + 12][m], p, acc3);
    }
    float b = ob[g * DG + o];
    Att[(size_t)(n0 + grp)      * FEAT + g * DG + o] = acc0 + b;
    Att[(size_t)(n0 + grp + 4)  * FEAT + g * DG + o] = acc1 + b;
    Att[(size_t)(n0 + grp + 8)  * FEAT + g * DG + o] = acc2 + b;
    Att[(size_t)(n0 + grp + 12) * FEAT + g * DG + o] = acc3 + b;
}

// ---------------- host-side helpers -------------------------------------------
static inline void split_launch(const float* src, __half* dh, __half* dl, int n) {
    int n4 = n / 4;
    split_f16<<<(n4 + 255) / 256, 256>>>((const float4*)src, (__half2*)dh, (__half2*)dl, n4);
}
static inline void gemm_launch(const __half* ah, const __half* al,
                               const __half* wh, const __half* wl,
                               const float* bias, float* c, int M, int N, int K,
                               __half* dh = nullptr, __half* dl = nullptr) {
    dim3 grid(N / 128, (M + 127) / 128);
    gemm_lm<<<grid, 512, GSMEM>>>(ah, al, wh, wl, bias, c,
                                  (__half2*)dh, (__half2*)dl, M, N, K);
}

extern "C" void kernel_launch(void* const* d_in, const int* in_sizes, int n_in,
                              void* d_out, int out_size) {
    const float* x       = (const float*)d_in[0];
    const float* pos_emb = (const float*)d_in[1];
    const float* fc6_w   = (const float*)d_in[2];
    const float* fc6_b   = (const float*)d_in[3];
    const float* fc7_w   = (const float*)d_in[4];
    const float* fc7_b   = (const float*)d_in[5];
    const float* a1[8];
    const float* a2[8];
    for (int i = 0; i < 8; i++) a1[i] = (const float*)d_in[6 + i];
    for (int i = 0; i < 8; i++) a2[i] = (const float*)d_in[14 + i];

    cudaFuncSetAttribute(gemm_lm, cudaFuncAttributeMaxDynamicSharedMemorySize, GSMEM);
    cudaFuncSetAttribute(aff_mma, cudaFuncAttributeMaxDynamicSharedMemorySize, GSMEM);

    float *p_h, *p_h2, *p_q, *p_att, *p_kp, *p_w1, *p_w2, *p_aff, *p_bkp;
    cudaGetSymbolAddress((void**)&p_h,   g_h);
    cudaGetSymbolAddress((void**)&p_h2,  g_h2);
    cudaGetSymbolAddress((void**)&p_q,   g_q);
    cudaGetSymbolAddress((void**)&p_att, g_att);
    cudaGetSymbolAddress((void**)&p_kp,  g_kp);
    cudaGetSymbolAddress((void**)&p_w1,  g_w1);
    cudaGetSymbolAddress((void**)&p_w2,  g_w2);
    cudaGetSymbolAddress((void**)&p_aff, g_aff);
    cudaGetSymbolAddress((void**)&p_bkp, g_bkp);

    __half *xh, *xl, *w6h, *w6l, *w7h, *w7l, *qwh, *qwl, *kpwh, *kpwl;
    __half *ahh, *all, *bhh, *bll, *qsh, *qsl, *kph, *kpl;
    cudaGetSymbolAddress((void**)&xh,   g_xh);
    cudaGetSymbolAddress((void**)&xl,   g_xl);
    cudaGetSymbolAddress((void**)&w6h,  g_w6h);
    cudaGetSymbolAddress((void**)&w6l,  g_w6l);
    cudaGetSymbolAddress((void**)&w7h,  g_w7h);
    cudaGetSymbolAddress((void**)&w7l,  g_w7l);
    cudaGetSymbolAddress((void**)&qwh,  g_qwh);
    cudaGetSymbolAddress((void**)&qwl,  g_qwl);
    cudaGetSymbolAddress((void**)&kpwh, g_kpwh);
    cudaGetSymbolAddress((void**)&kpwl, g_kpwl);
    cudaGetSymbolAddress((void**)&ahh,  g_ah);
    cudaGetSymbolAddress((void**)&all,  g_al);
    cudaGetSymbolAddress((void**)&bhh,  g_bh);
    cudaGetSymbolAddress((void**)&bll,  g_bl);
    cudaGetSymbolAddress((void**)&qsh,  g_qsh);
    cudaGetSymbolAddress((void**)&qsl,  g_qsl);
    cudaGetSymbolAddress((void**)&kph,  g_kph);
    cudaGetSymbolAddress((void**)&kpl,  g_kpl);

    const int n4 = NTOK * FEAT / 4;
    const dim3 affGrid(3, NTOK / 128, G);

    // ---- fc6 (fused split -> ahh/all) + pos weights ----
    split_launch(x,     xh,  xl,  NTOK * IN_CH);
    split_launch(fc6_w, w6h, w6l, FEAT * IN_CH);
    split_launch(fc7_w, w7h, w7l, FEAT * FEAT);
    pos_dual<<<NTOK, 256>>>(pos_emb, a1[0], a1[1], a2[0], a2[1], p_w1, p_w2);
    gemm_launch(xh, xl, w6h, w6l, fc6_b, p_h, NTOK, FEAT, IN_CH, ahh, all);

    // ---- attention 1 ----
    split_launch(a1[2], qwh, qwl, FEAT * FEAT);
    split_launch(a1[4], kpwh, kpwl, FEAT * FEAT);
    split_launch(a1[6], kpwh + 1024 * FEAT, kpwl + 1024 * FEAT, FEAT * FEAT);
    build_bias_kp<<<8, 256>>>(a1[5], p_bkp);

    gemm_launch(ahh, all, qwh, qwl, a1[3], p_q, NTOK, FEAT, FEAT, qsh, qsl);
    gemm_launch(ahh, all, kpwh, kpwl, p_bkp, p_kp, NONGT, 2048, FEAT, kph, kpl);
    aff_mma<<<affGrid, 512, GSMEM>>>(qsh, qsl, kph, kpl, p_aff);
    softmax_pv<<<dim3(NTOK / 16, G), 256>>>(p_w1, p_aff, p_kp + 1024, 2048, a1[7], p_att);

    // ---- h2 = relu(h + att1) -> bhh/bll ----
    addrelu_split<<<(n4 + 255) / 256, 256>>>((const float4*)p_h, (const float4*)p_att,
                                             (__half2*)bhh, (__half2*)bll, n4);

    // ---- fc7 (fused split -> ahh/all) ----
    gemm_launch(bhh, bll, w7h, w7l, fc7_b, p_h2, NTOK, FEAT, FEAT, ahh, all);

    // ---- attention 2 ----
    split_launch(a2[2], qwh, qwl, FEAT * FEAT);
    split_launch(a2[4], kpwh, kpwl, FEAT * FEAT);
    split_launch(a2[6], kpwh + 1024 * FEAT, kpwl + 1024 * FEAT, FEAT * FEAT);
    build_bias_kp<<<8, 256>>>(a2[5], p_bkp);

    gemm_launch(ahh, all, qwh, qwl, a2[3], p_q, NTOK, FEAT, FEAT, qsh, qsl);
    gemm_launch(ahh, all, kpwh, kpwl, p_bkp, p_kp, NONGT, 2048, FEAT, kph, kpl);
    aff_mma<<<affGrid, 512, GSMEM>>>(qsh, qsl, kph, kpl, p_aff);
    softmax_pv<<<dim3(NTOK / 16, G), 256>>>(p_w2, p_aff, p_kp + 1024, 2048, a2[7], p_att);

    // ---- out = relu(h2 + att2) ----
    add_relu4<<<(n4 + 255) / 256, 256>>>((const float4*)p_h2, (const float4*)p_att,
                                         (float4*)d_out, n4);
}

// round 17
// speedup vs baseline: 1.0631x; 1.0631x over previous
#include <cuda_runtime.h>
#include <cuda_fp16.h>
#include <math.h>
#include <stdint.h>

#define NTOK   2048
#define FEAT   1024
#define IN_CH  12544
#define NONGT  300
#define G      16
#define DG     64
#define EMB    64
#define GW_STRIDE (G * NONGT)   // 4800

// GEMM tile config: 128x128 CTA tile, BK=16, 512 threads, ldmatrix, 4-stage cp.async
#define ROWB   48
#define TILEB  (128 * ROWB)
#define STGB   (4 * TILEB)
#define GSMEM  (4 * STGB)        // 98304 B

// ---------------- fp32 scratch ----------------
__device__ float g_h   [NTOK * FEAT];
__device__ float g_h2  [NTOK * FEAT];
__device__ float g_q   [NTOK * FEAT];
__device__ float g_att [NTOK * FEAT];
__device__ float g_kp  [384 * 2048];
__device__ float g_w1  [NTOK * G * NONGT];
__device__ float g_w2  [NTOK * G * NONGT];
__device__ float g_aff [NTOK * G * NONGT];
__device__ float g_bkp [2048];

// ---------------- fp16 split scratch ----------------
__device__ __half g_xh [NTOK * IN_CH];
__device__ __half g_xl [NTOK * IN_CH];
__device__ __half g_w6h[FEAT * IN_CH];
__device__ __half g_w6l[FEAT * IN_CH];
__device__ __half g_w7h[FEAT * FEAT];
__device__ __half g_w7l[FEAT * FEAT];
__device__ __half g_qwh[FEAT * FEAT];
__device__ __half g_qwl[FEAT * FEAT];
__device__ __half g_kpwh[2048 * FEAT];
__device__ __half g_kpwl[2048 * FEAT];
__device__ __half g_ah [NTOK * FEAT];
__device__ __half g_al [NTOK * FEAT];
__device__ __half g_bh [NTOK * FEAT];
__device__ __half g_bl [NTOK * FEAT];
__device__ __half g_qsh[NTOK * FEAT];
__device__ __half g_qsl[NTOK * FEAT];
__device__ __half g_kph[384 * 2048];
__device__ __half g_kpl[384 * 2048];

// ---------------- helpers ----------------
__device__ __forceinline__ uint32_t cvta_s(const void* p) {
    return (uint32_t)__cvta_generic_to_shared(p);
}
__device__ __forceinline__ void cp16(uint32_t s, const void* g) {
    asm volatile("cp.async.cg.shared.global [%0], [%1], 16;\n" :: "r"(s), "l"(g));
}
#define LDSM_X4(r0, r1, r2, r3, a)                                              \
    asm volatile("ldmatrix.sync.aligned.m8n8.x4.shared.b16 {%0,%1,%2,%3}, [%4];" \
                 : "=r"(r0), "=r"(r1), "=r"(r2), "=r"(r3) : "r"(a))
#define MMA16(ACC, A0, A1, A2, A3, B0, B1)                                      \
    asm volatile(                                                               \
        "mma.sync.aligned.m16n8k16.row.col.f32.f16.f16.f32 "                    \
        "{%0,%1,%2,%3}, {%4,%5,%6,%7}, {%8,%9}, {%0,%1,%2,%3};\n"               \
        : "+f"(ACC[0]), "+f"(ACC[1]), "+f"(ACC[2]), "+f"(ACC[3])                \
        : "r"(A0), "r"(A1), "r"(A2), "r"(A3), "r"(B0), "r"(B1))

// ---------------- fp16x3 GEMM, 512 threads: C = A[M,K] @ W[N,K]^T (+bias) ----
__global__ __launch_bounds__(512, 1)
void gemm_lm(const __half* __restrict__ Ah, const __half* __restrict__ Al,
             const __half* __restrict__ Wh, const __half* __restrict__ Wl,
             const float* __restrict__ bias, float* __restrict__ C,
             __half2* __restrict__ dH, __half2* __restrict__ dL,
             int M, int N, int K) {
    extern __shared__ char dsm[];
    const uint32_t sbase = cvta_s(dsm);

    const int tid  = threadIdx.x;
    const int lane = tid & 31;
    const int wid  = tid >> 5;
    const int wm   = wid >> 2;
    const int wn   = wid & 3;
    const int qd   = lane >> 2;
    const int tg   = lane & 3;
    const int bm   = blockIdx.y * 128;
    const int bn   = blockIdx.x * 128;

    const int lrow = (tid & 255) >> 1;
    const int lch  = tid & 1;
    const bool isA = tid < 256;
    const __half* gH = (isA ? Ah + (size_t)(bm + lrow) * K
                            : Wh + (size_t)(bn + lrow) * K) + lch * 8;
    const __half* gL = (isA ? Al + (size_t)(bm + lrow) * K
                            : Wl + (size_t)(bn + lrow) * K) + lch * 8;
    const uint32_t woffH = (uint32_t)((isA ? 0 : 2 * TILEB) + lrow * ROWB + lch * 16);

    const uint32_t aRow  = (uint32_t)(wm * 32 + (lane & 7) + ((lane >> 3) & 1) * 8);
    const uint32_t aByte = (uint32_t)(((lane >> 4) & 1) * 16);
    const uint32_t bRow  = (uint32_t)(wn * 32 + ((lane >> 4) & 1) * 8 + (lane & 7));
    const uint32_t bByte = (uint32_t)(((lane >> 3) & 1) * 16);

    float acc[2][4][4];
#pragma unroll
    for (int i = 0; i < 2; i++)
#pragma unroll
        for (int j = 0; j < 4; j++)
#pragma unroll
            for (int r = 0; r < 4; r++) acc[i][j][r] = 0.f;

    const int nk = K / 16;

    auto load_stage = [&](int kt) {
        const uint32_t st = sbase + (uint32_t)(kt & 3) * STGB;
        const size_t k0 = (size_t)kt * 16;
        cp16(st + woffH, gH + k0);
        cp16(st + TILEB + woffH, gL + k0);
    };

#pragma unroll
    for (int s = 0; s < 3; s++) {
        if (s < nk) load_stage(s);
        asm volatile("cp.async.commit_group;\n");
    }

    for (int kt = 0; kt < nk; kt++) {
        asm volatile("cp.async.wait_group 2;\n");
        __syncthreads();
        if (kt + 3 < nk) load_stage(kt + 3);
        asm volatile("cp.async.commit_group;\n");

        const uint32_t st = sbase + (uint32_t)(kt & 3) * STGB;

        uint32_t ah[2][4], al_[2][4], bh[4][2], bl[4][2];
#pragma unroll
        for (int mi = 0; mi < 2; mi++) {
            const uint32_t ar = (aRow + mi * 16) * ROWB + aByte;
            LDSM_X4(ah[mi][0], ah[mi][1], ah[mi][2], ah[mi][3], st + ar);
            LDSM_X4(al_[mi][0], al_[mi][1], al_[mi][2], al_[mi][3], st + TILEB + ar);
        }
        {
            const uint32_t br = bRow * ROWB + bByte;
            uint32_t r0, r1, r2, r3;
            LDSM_X4(r0, r1, r2, r3, st + 2 * TILEB + br);
            bh[0][0] = r0; bh[0][1] = r1; bh[1][0] = r2; bh[1][1] = r3;
            LDSM_X4(r0, r1, r2, r3, st + 2 * TILEB + br + 16 * ROWB);
            bh[2][0] = r0; bh[2][1] = r1; bh[3][0] = r2; bh[3][1] = r3;
            LDSM_X4(r0, r1, r2, r3, st + 3 * TILEB + br);
            bl[0][0] = r0; bl[0][1] = r1; bl[1][0] = r2; bl[1][1] = r3;
            LDSM_X4(r0, r1, r2, r3, st + 3 * TILEB + br + 16 * ROWB);
            bl[2][0] = r0; bl[2][1] = r1; bl[3][0] = r2; bl[3][1] = r3;
        }

#pragma unroll
        for (int mi = 0; mi < 2; mi++)
#pragma unroll
            for (int ni = 0; ni < 4; ni++)
                MMA16(acc[mi][ni], al_[mi][0], al_[mi][1], al_[mi][2], al_[mi][3],
                      bh[ni][0], bh[ni][1]);
#pragma unroll
        for (int mi = 0; mi < 2; mi++)
#pragma unroll
            for (int ni = 0; ni < 4; ni++)
                MMA16(acc[mi][ni], ah[mi][0], ah[mi][1], ah[mi][2], ah[mi][3],
                      bl[ni][0], bl[ni][1]);
#pragma unroll
        for (int mi = 0; mi < 2; mi++)
#pragma unroll
            for (int ni = 0; ni < 4; ni++)
                MMA16(acc[mi][ni], ah[mi][0], ah[mi][1], ah[mi][2], ah[mi][3],
                      bh[ni][0], bh[ni][1]);
    }

#pragma unroll
    for (int mi = 0; mi < 2; mi++) {
        const int r0 = bm + wm * 32 + mi * 16 + qd;
#pragma unroll
        for (int ni = 0; ni < 4; ni++) {
            const int c0 = bn + wn * 32 + ni * 8 + tg * 2;
            const float b0 = bias ? bias[c0]     : 0.f;
            const float b1 = bias ? bias[c0 + 1] : 0.f;
#pragma unroll
            for (int half = 0; half < 2; half++) {
                const int r = r0 + half * 8;
                if (r < M) {
                    const float vx = acc[mi][ni][half * 2]     + b0;
                    const float vy = acc[mi][ni][half * 2 + 1] + b1;
                    const size_t idx = (size_t)r * N + c0;
                    *(float2*)(C + idx) = make_float2(vx, vy);
                    if (dH) {
                        __half2 h = __floats2half2_rn(vx, vy);
                        float2 f = __half22float2(h);
                        dH[idx >> 1] = h;
                        dL[idx >> 1] = __floats2half2_rn(vx - f.x, vy - f.y);
                    }
                }
            }
        }
    }
}

// ---------------- aff via tensor cores (validated R14) ------------------------
__global__ __launch_bounds__(512, 1)
void aff_mma(const __half* __restrict__ Qh, const __half* __restrict__ Ql,
             const __half* __restrict__ Kh, const __half* __restrict__ Kl,
             float* __restrict__ Aff) {
    extern __shared__ char dsm[];
    const uint32_t sbase = cvta_s(dsm);

    const int tid  = threadIdx.x;
    const int lane = tid & 31;
    const int wid  = tid >> 5;
    const int wm   = wid >> 2;
    const int wn   = wid & 3;
    const int qd   = lane >> 2;
    const int tg   = lane & 3;
    const int g    = blockIdx.z;
    const int bm   = blockIdx.y * 128;   // n tile
    const int bn   = blockIdx.x * 128;   // m tile

    const int lrow = (tid & 255) >> 1;
    const int lch  = tid & 1;
    const bool isA = tid < 256;
    const __half* gH = (isA ? Qh + (size_t)(bm + lrow) * FEAT
                            : Kh + (size_t)(bn + lrow) * 2048) + g * DG + lch * 8;
    const __half* gL = (isA ? Ql + (size_t)(bm + lrow) * FEAT
                            : Kl + (size_t)(bn + lrow) * 2048) + g * DG + lch * 8;
    const uint32_t woffH = (uint32_t)((isA ? 0 : 2 * TILEB) + lrow * ROWB + lch * 16);

    const uint32_t aRow  = (uint32_t)(wm * 32 + (lane & 7) + ((lane >> 3) & 1) * 8);
    const uint32_t aByte = (uint32_t)(((lane >> 4) & 1) * 16);
    const uint32_t bRow  = (uint32_t)(wn * 32 + ((lane >> 4) & 1) * 8 + (lane & 7));
    const uint32_t bByte = (uint32_t)(((lane >> 3) & 1) * 16);

    float acc[2][4][4];
#pragma unroll
    for (int i = 0; i < 2; i++)
#pragma unroll
        for (int j = 0; j < 4; j++)
#pragma unroll
            for (int r = 0; r < 4; r++) acc[i][j][r] = 0.f;

    auto load_stage = [&](int kt) {
        const uint32_t st = sbase + (uint32_t)(kt & 3) * STGB;
        const size_t k0 = (size_t)kt * 16;
        cp16(st + woffH, gH + k0);
        cp16(st + TILEB + woffH, gL + k0);
    };

#pragma unroll
    for (int s = 0; s < 3; s++) {
        load_stage(s);
        asm volatile("cp.async.commit_group;\n");
    }

#pragma unroll
    for (int kt = 0; kt < 4; kt++) {
        asm volatile("cp.async.wait_group 2;\n");
        __syncthreads();
        if (kt == 0) load_stage(3);
        asm volatile("cp.async.commit_group;\n");

        const uint32_t st = sbase + (uint32_t)(kt & 3) * STGB;

        uint32_t ah[2][4], al_[2][4], bh[4][2], bl[4][2];
#pragma unroll
        for (int mi = 0; mi < 2; mi++) {
            const uint32_t ar = (aRow + mi * 16) * ROWB + aByte;
            LDSM_X4(ah[mi][0], ah[mi][1], ah[mi][2], ah[mi][3], st + ar);
            LDSM_X4(al_[mi][0], al_[mi][1], al_[mi][2], al_[mi][3], st + TILEB + ar);
        }
        {
            const uint32_t br = bRow * ROWB + bByte;
            uint32_t r0, r1, r2, r3;
            LDSM_X4(r0, r1, r2, r3, st + 2 * TILEB + br);
            bh[0][0] = r0; bh[0][1] = r1; bh[1][0] = r2; bh[1][1] = r3;
            LDSM_X4(r0, r1, r2, r3, st + 2 * TILEB + br + 16 * ROWB);
            bh[2][0] = r0; bh[2][1] = r1; bh[3][0] = r2; bh[3][1] = r3;
            LDSM_X4(r0, r1, r2, r3, st + 3 * TILEB + br);
            bl[0][0] = r0; bl[0][1] = r1; bl[1][0] = r2; bl[1][1] = r3;
            LDSM_X4(r0, r1, r2, r3, st + 3 * TILEB + br + 16 * ROWB);
            bl[2][0] = r0; bl[2][1] = r1; bl[3][0] = r2; bl[3][1] = r3;
        }

#pragma unroll
        for (int mi = 0; mi < 2; mi++)
#pragma unroll
            for (int ni = 0; ni < 4; ni++)
                MMA16(acc[mi][ni], al_[mi][0], al_[mi][1], al_[mi][2], al_[mi][3],
                      bh[ni][0], bh[ni][1]);
#pragma unroll
        for (int mi = 0; mi < 2; mi++)
#pragma unroll
            for (int ni = 0; ni < 4; ni++)
                MMA16(acc[mi][ni], ah[mi][0], ah[mi][1], ah[mi][2], ah[mi][3],
                      bl[ni][0], bl[ni][1]);
#pragma unroll
        for (int mi = 0; mi < 2; mi++)
#pragma unroll
            for (int ni = 0; ni < 4; ni++)
                MMA16(acc[mi][ni], ah[mi][0], ah[mi][1], ah[mi][2], ah[mi][3],
                      bh[ni][0], bh[ni][1]);
    }

#pragma unroll
    for (int mi = 0; mi < 2; mi++) {
        const int r0 = bm + wm * 32 + mi * 16 + qd;
#pragma unroll
        for (int ni = 0; ni < 4; ni++) {
            const int c0 = bn + wn * 32 + ni * 8 + tg * 2;
            if (c0 < NONGT) {
#pragma unroll
                for (int half = 0; half < 2; half++) {
                    const int r = r0 + half * 8;
                    float* dst = Aff + (size_t)r * GW_STRIDE + g * NONGT + c0;
                    *(float2*)dst = make_float2(0.125f * acc[mi][ni][half * 2],
                                                0.125f * acc[mi][ni][half * 2 + 1]);
                }
            }
        }
    }
}

// ---------------- split: fp32 -> (hi, lo) fp16 --------------------------------
__global__ void split_f16(const float4* __restrict__ src, __half2* __restrict__ dh,
                          __half2* __restrict__ dl, int n4) {
    int i = blockIdx.x * blockDim.x + threadIdx.x;
    if (i < n4) {
        float4 v = src[i];
        __half2 h0 = __floats2half2_rn(v.x, v.y);
        __half2 h1 = __floats2half2_rn(v.z, v.w);
        float2 f0 = __half22float2(h0);
        float2 f1 = __half22float2(h1);
        dh[i * 2]     = h0;
        dh[i * 2 + 1] = h1;
        dl[i * 2]     = __floats2half2_rn(v.x - f0.x, v.y - f0.y);
        dl[i * 2 + 1] = __floats2half2_rn(v.z - f1.x, v.w - f1.y);
    }
}

// ---------------- h2 = relu(a+b), emitted as fp16 split -----------------------
__global__ void addrelu_split(const float4* __restrict__ a, const float4* __restrict__ b,
                              __half2* __restrict__ dh, __half2* __restrict__ dl, int n4) {
    int i = blockIdx.x * blockDim.x + threadIdx.x;
    if (i < n4) {
        float4 x = a[i], y = b[i];
        float4 v;
        v.x = fmaxf(x.x + y.x, 0.f); v.y = fmaxf(x.y + y.y, 0.f);
        v.z = fmaxf(x.z + y.z, 0.f); v.w = fmaxf(x.w + y.w, 0.f);
        __half2 h0 = __floats2half2_rn(v.x, v.y);
        __half2 h1 = __floats2half2_rn(v.z, v.w);
        float2 f0 = __half22float2(h0);
        float2 f1 = __half22float2(h1);
        dh[i * 2]     = h0;
        dh[i * 2 + 1] = h1;
        dl[i * 2]     = __floats2half2_rn(v.x - f0.x, v.y - f0.y);
        dl[i * 2 + 1] = __floats2half2_rn(v.z - f1.x, v.w - f1.y);
    }
}

// ---------------- final: c = relu(a+b) fp32 -----------------------------------
__global__ void add_relu4(const float4* __restrict__ a, const float4* __restrict__ b,
                          float4* __restrict__ c, int n4) {
    int i = blockIdx.x * blockDim.x + threadIdx.x;
    if (i < n4) {
        float4 x = a[i], y = b[i];
        float4 r;
        r.x = fmaxf(x.x + y.x, 0.f); r.y = fmaxf(x.y + y.y, 0.f);
        r.z = fmaxf(x.z + y.z, 0.f); r.w = fmaxf(x.w + y.w, 0.f);
        c[i] = r;
    }
}

// ---------------- bias for fused k|P GEMM -------------------------------------
__global__ void build_bias_kp(const float* __restrict__ kb, float* __restrict__ dst) {
    int i = blockIdx.x * blockDim.x + threadIdx.x;
    if (i < 2048) dst[i] = (i < 1024) ? kb[i] : 0.f;
}

// ---------------- pos weights v4: v2 layout + 4x m-tile (FMA-bound) -----------
// W{1,2}[n][g][m] = max(relu(pos_emb[n,m]·pw{1,2}[g] + pb{1,2}[g]), 1e-6)
__global__ __launch_bounds__(256)
void pos_dual(const float* __restrict__ pos_emb,
              const float* __restrict__ pw1, const float* __restrict__ pb1,
              const float* __restrict__ pw2, const float* __restrict__ pb2,
              float* __restrict__ W1, float* __restrict__ W2) {
    const int n = blockIdx.x;
    __shared__ float pws[32][65];     // rows 0..15: layer1, 16..31: layer2
    __shared__ float pbs[32];
    __shared__ float pe[128][65];     // 128-m chunk
    const int tid = threadIdx.x;

    if (tid < 16) pbs[tid] = pb1[tid];
    else if (tid < 32) pbs[tid] = pb2[tid - 16];
    {   // weights: 32 rows x 64, each thread 8 floats
        int row = tid >> 3;
        int c = (tid & 7) * 8;
        const float* src = (row < 16) ? pw1 + row * 64 + c : pw2 + (row - 16) * 64 + c;
        float4 v0 = *(const float4*)src;
        float4 v1 = *(const float4*)(src + 4);
        pws[row][c + 0] = v0.x; pws[row][c + 1] = v0.y;
        pws[row][c + 2] = v0.z; pws[row][c + 3] = v0.w;
        pws[row][c + 4] = v1.x; pws[row][c + 5] = v1.y;
        pws[row][c + 6] = v1.z; pws[row][c + 7] = v1.w;
    }
    __syncthreads();

    const int w = tid >> 5, lane = tid & 31;
    const int g0 = w * 2, g1 = g0 + 1;
    const float b10 = pbs[g0], b11 = pbs[g1];
    const float b20 = pbs[16 + g0], b21 = pbs[16 + g1];
    const size_t nbase = (size_t)n * GW_STRIDE;

    for (int mc = 0; mc < 3; mc++) {          // chunks: 128, 128, 44
        const int m0 = mc * 128;
        {   // load pe chunk: up to 128 rows x 64, each thread 2 rows x 16 floats
            int r = tid >> 1;                  // 0..127
            int c = (tid & 1) * 32;            // 0 or 32
            int m = m0 + r;
            if (m < NONGT) {
                const float4* src = (const float4*)(pos_emb + ((size_t)n * NONGT + m) * EMB + c);
#pragma unroll
                for (int j = 0; j < 8; j++) {
                    float4 v = __ldg(src + j);
                    pe[r][c + j * 4 + 0] = v.x; pe[r][c + j * 4 + 1] = v.y;
                    pe[r][c + j * 4 + 2] = v.z; pe[r][c + j * 4 + 3] = v.w;
                }
            }
        }
        __syncthreads();

        // 4 m's per thread: lane, lane+32, lane+64, lane+96
        float a1v[4][2], a2v[4][2];
#pragma unroll
        for (int t = 0; t < 4; t++) {
            a1v[t][0] = b10; a1v[t][1] = b11;
            a2v[t][0] = b20; a2v[t][1] = b21;
        }
#pragma unroll
        for (int e = 0; e < 64; e++) {
            const float w10 = pws[g0][e],      w11 = pws[g1][e];
            const float w20 = pws[16 + g0][e], w21 = pws[16 + g1][e];
#pragma unroll
            for (int t = 0; t < 4; t++) {
                const float p = pe[lane + t * 32][e];
                a1v[t][0] = fmaf(p, w10, a1v[t][0]);
                a1v[t][1] = fmaf(p, w11, a1v[t][1]);
                a2v[t][0] = fmaf(p, w20, a2v[t][0]);
                a2v[t][1] = fmaf(p, w21, a2v[t][1]);
            }
        }
#pragma unroll
        for (int t = 0; t < 4; t++) {
            const int m = m0 + lane + t * 32;
            if (m < NONGT) {
                W1[nbase + g0 * NONGT + m] = fmaxf(a1v[t][0], 1e-6f);
                W1[nbase + g1 * NONGT + m] = fmaxf(a1v[t][1], 1e-6f);
                W2[nbase + g0 * NONGT + m] = fmaxf(a2v[t][0], 1e-6f);
                W2[nbase + g1 * NONGT + m] = fmaxf(a2v[t][1], 1e-6f);
            }
        }
        __syncthreads();
    }
}

// ---------------- softmax(w * e^aff) over m + out = s @ P_g + out_b ----------
__global__ __launch_bounds__(256)
void softmax_pv(const float* __restrict__ Wt, const float* __restrict__ Aff,
                const float* __restrict__ P, int ldp,
                const float* __restrict__ ob, float* __restrict__ Att) {
    const int g  = blockIdx.y;
    const int n0 = blockIdx.x * 16;
    __shared__ float s[16][301];
    const int tid = threadIdx.x, w = tid >> 5, lane = tid & 31;

#pragma unroll
    for (int rr = 0; rr < 2; rr++) {
        int r = w * 2 + rr;
        const float* srcW = Wt  + (size_t)(n0 + r) * GW_STRIDE + g * NONGT;
        const float* srcA = Aff + (size_t)(n0 + r) * GW_STRIDE + g * NONGT;
        float a[10], wv[10];
        float mx = -1e30f;
#pragma unroll
        for (int i = 0; i < 10; i++) {
            int m = lane + 32 * i;
            a[i]  = (m < NONGT) ? srcA[m] : -1e30f;
            wv[i] = (m < NONGT) ? srcW[m] : 0.f;
            mx = fmaxf(mx, a[i]);
        }
#pragma unroll
        for (int off = 16; off; off >>= 1) mx = fmaxf(mx, __shfl_xor_sync(~0u, mx, off));
        float sum = 0.f;
#pragma unroll
        for (int i = 0; i < 10; i++) {
            float e = wv[i] * __expf(a[i] - mx);
            a[i] = e;
            sum += e;
        }
#pragma unroll
        for (int off = 16; off; off >>= 1) sum += __shfl_xor_sync(~0u, sum, off);
        float inv = 1.f / sum;
#pragma unroll
        for (int i = 0; i < 10; i++) {
            int m = lane + 32 * i;
            if (m < NONGT) s[r][m] = a[i] * inv;
        }
    }
    __syncthreads();

    const int o = tid & 63, grp = tid >> 6;
    float acc0 = 0.f, acc1 = 0.f, acc2 = 0.f, acc3 = 0.f;
    const float* pcol = P + g * DG + o;
#pragma unroll 4
    for (int m = 0; m < NONGT; m++) {
        float p = __ldg(pcol + (size_t)m * ldp);
        acc0 = fmaf(s[grp][m],      p, acc0);
        acc1 = fmaf(s[grp + 4][m],  p, acc1);
        acc2 = fmaf(s[grp + 8][m],  p, acc2);
        acc3 = fmaf(s[grp + 12][m], p, acc3);
    }
    float b = ob[g * DG + o];
    Att[(size_t)(n0 + grp)      * FEAT + g * DG + o] = acc0 + b;
    Att[(size_t)(n0 + grp + 4)  * FEAT + g * DG + o] = acc1 + b;
    Att[(size_t)(n0 + grp + 8)  * FEAT + g * DG + o] = acc2 + b;
    Att[(size_t)(n0 + grp + 12) * FEAT + g * DG + o] = acc3 + b;
}

// ---------------- host-side helpers -------------------------------------------
static inline void split_launch(const float* src, __half* dh, __half* dl, int n) {
    int n4 = n / 4;
    split_f16<<<(n4 + 255) / 256, 256>>>((const float4*)src, (__half2*)dh, (__half2*)dl, n4);
}
static inline void gemm_launch(const __half* ah, const __half* al,
                               const __half* wh, const __half* wl,
                               const float* bias, float* c, int M, int N, int K,
                               __half* dh = nullptr, __half* dl = nullptr) {
    dim3 grid(N / 128, (M + 127) / 128);
    gemm_lm<<<grid, 512, GSMEM>>>(ah, al, wh, wl, bias, c,
                                  (__half2*)dh, (__half2*)dl, M, N, K);
}

extern "C" void kernel_launch(void* const* d_in, const int* in_sizes, int n_in,
                              void* d_out, int out_size) {
    const float* x       = (const float*)d_in[0];
    const float* pos_emb = (const float*)d_in[1];
    const float* fc6_w   = (const float*)d_in[2];
    const float* fc6_b   = (const float*)d_in[3];
    const float* fc7_w   = (const float*)d_in[4];
    const float* fc7_b   = (const float*)d_in[5];
    const float* a1[8];
    const float* a2[8];
    for (int i = 0; i < 8; i++) a1[i] = (const float*)d_in[6 + i];
    for (int i = 0; i < 8; i++) a2[i] = (const float*)d_in[14 + i];

    cudaFuncSetAttribute(gemm_lm, cudaFuncAttributeMaxDynamicSharedMemorySize, GSMEM);
    cudaFuncSetAttribute(aff_mma, cudaFuncAttributeMaxDynamicSharedMemorySize, GSMEM);

    float *p_h, *p_h2, *p_q, *p_att, *p_kp, *p_w1, *p_w2, *p_aff, *p_bkp;
    cudaGetSymbolAddress((void**)&p_h,   g_h);
    cudaGetSymbolAddress((void**)&p_h2,  g_h2);
    cudaGetSymbolAddress((void**)&p_q,   g_q);
    cudaGetSymbolAddress((void**)&p_att, g_att);
    cudaGetSymbolAddress((void**)&p_kp,  g_kp);
    cudaGetSymbolAddress((void**)&p_w1,  g_w1);
    cudaGetSymbolAddress((void**)&p_w2,  g_w2);
    cudaGetSymbolAddress((void**)&p_aff, g_aff);
    cudaGetSymbolAddress((void**)&p_bkp, g_bkp);

    __half *xh, *xl, *w6h, *w6l, *w7h, *w7l, *qwh, *qwl, *kpwh, *kpwl;
    __half *ahh, *all, *bhh, *bll, *qsh, *qsl, *kph, *kpl;
    cudaGetSymbolAddress((void**)&xh,   g_xh);
    cudaGetSymbolAddress((void**)&xl,   g_xl);
    cudaGetSymbolAddress((void**)&w6h,  g_w6h);
    cudaGetSymbolAddress((void**)&w6l,  g_w6l);
    cudaGetSymbolAddress((void**)&w7h,  g_w7h);
    cudaGetSymbolAddress((void**)&w7l,  g_w7l);
    cudaGetSymbolAddress((void**)&qwh,  g_qwh);
    cudaGetSymbolAddress((void**)&qwl,  g_qwl);
    cudaGetSymbolAddress((void**)&kpwh, g_kpwh);
    cudaGetSymbolAddress((void**)&kpwl, g_kpwl);
    cudaGetSymbolAddress((void**)&ahh,  g_ah);
    cudaGetSymbolAddress((void**)&all,  g_al);
    cudaGetSymbolAddress((void**)&bhh,  g_bh);
    cudaGetSymbolAddress((void**)&bll,  g_bl);
    cudaGetSymbolAddress((void**)&qsh,  g_qsh);
    cudaGetSymbolAddress((void**)&qsl,  g_qsl);
    cudaGetSymbolAddress((void**)&kph,  g_kph);
    cudaGetSymbolAddress((void**)&kpl,  g_kpl);

    const int n4 = NTOK * FEAT / 4;
    const dim3 affGrid(3, NTOK / 128, G);

    // ---- fc6 (fused split -> ahh/all) + pos weights ----
    split_launch(x,     xh,  xl,  NTOK * IN_CH);
    split_launch(fc6_w, w6h, w6l, FEAT * IN_CH);
    split_launch(fc7_w, w7h, w7l, FEAT * FEAT);
    pos_dual<<<NTOK, 256>>>(pos_emb, a1[0], a1[1], a2[0], a2[1], p_w1, p_w2);
    gemm_launch(xh, xl, w6h, w6l, fc6_b, p_h, NTOK, FEAT, IN_CH, ahh, all);

    // ---- attention 1 ----
    split_launch(a1[2], qwh, qwl, FEAT * FEAT);
    split_launch(a1[4], kpwh, kpwl, FEAT * FEAT);
    split_launch(a1[6], kpwh + 1024 * FEAT, kpwl + 1024 * FEAT, FEAT * FEAT);
    build_bias_kp<<<8, 256>>>(a1[5], p_bkp);

    gemm_launch(ahh, all, qwh, qwl, a1[3], p_q, NTOK, FEAT, FEAT, qsh, qsl);
    gemm_launch(ahh, all, kpwh, kpwl, p_bkp, p_kp, NONGT, 2048, FEAT, kph, kpl);
    aff_mma<<<affGrid, 512, GSMEM>>>(qsh, qsl, kph, kpl, p_aff);
    softmax_pv<<<dim3(NTOK / 16, G), 256>>>(p_w1, p_aff, p_kp + 1024, 2048, a1[7], p_att);

    // ---- h2 = relu(h + att1) -> bhh/bll ----
    addrelu_split<<<(n4 + 255) / 256, 256>>>((const float4*)p_h, (const float4*)p_att,
                                             (__half2*)bhh, (__half2*)bll, n4);

    // ---- fc7 (fused split -> ahh/all) ----
    gemm_launch(bhh, bll, w7h, w7l, fc7_b, p_h2, NTOK, FEAT, FEAT, ahh, all);

    // ---- attention 2 ----
    split_launch(a2[2], qwh, qwl, FEAT * FEAT);
    split_launch(a2[4], kpwh, kpwl, FEAT * FEAT);
    split_launch(a2[6], kpwh + 1024 * FEAT, kpwl + 1024 * FEAT, FEAT * FEAT);
    build_bias_kp<<<8, 256>>>(a2[5], p_bkp);

    gemm_launch(ahh, all, qwh, qwl, a2[3], p_q, NTOK, FEAT, FEAT, qsh, qsl);
    gemm_launch(ahh, all, kpwh, kpwl, p_bkp, p_kp, NONGT, 2048, FEAT, kph, kpl);
    aff_mma<<<affGrid, 512, GSMEM>>>(qsh, qsl, kph, kpl, p_aff);
    softmax_pv<<<dim3(NTOK / 16, G), 256>>>(p_w2, p_aff, p_kp + 1024, 2048, a2[7], p_att);

    // ---- out = relu(h2 + att2) ----
    add_relu4<<<(n4 + 255) / 256, 256>>>((const float4*)p_h2, (const float4*)p_att,
                                         (float4*)d_out, n4);
}